// round 12
// baseline (speedup 1.0000x reference)
#include <cuda_runtime.h>
#include <cuda_bf16.h>
#include <cstdint>

#define Bv   128
#define Hv   256
#define Tv   2048
#define Vv   32000
#define NTILES 250            // Vv / 128

#define LOGP_OFF  0
#define HNEW_OFF  (Bv*Vv)                 // 4,096,000
#define ATTN_OFF  (HNEW_OFF + Bv*Hv)      // 4,128,768
#define CTX_OFF   (ATTN_OFF + Bv*Tv)      // 4,390,912

#define NEG_HUGE  (-3.402823466e38f)

// ---------------- scratch ----------------
__device__ __align__(16) float g_x[Bv * Hv];       // relu(comb) [b][n]
__device__ __align__(16) float g_gx[Bv * 3 * Hv];
__device__ __align__(16) float g_gh[Bv * 3 * Hv];
__device__ __align__(16) float g_pmax[Bv * NTILES];  // [b][tile] coalesced
__device__ __align__(16) float g_psum[Bv * NTILES];
__device__ __align__(16) float g_am[2 * Bv];        // attn chunk partials
__device__ __align__(16) float g_al[2 * Bv];
__device__ __align__(16) float g_actx[2 * Bv * Hv];
__device__ unsigned long long g_bar = 0ull;        // k_mid barrier (nb=128)

// ---------------- helpers ----------------
__device__ __forceinline__ uint32_t to_tf32(float x) {
    uint32_t r;
    asm("cvt.rna.tf32.f32 %0, %1;" : "=r"(r) : "f"(x));
    return r;
}
__device__ __forceinline__ void mma_tf32(float* c, uint32_t a0, uint32_t a1,
                                         uint32_t a2, uint32_t a3,
                                         uint32_t b0, uint32_t b1) {
    asm("mma.sync.aligned.m16n8k8.row.col.f32.tf32.tf32.f32 "
        "{%0,%1,%2,%3},{%4,%5,%6,%7},{%8,%9},{%0,%1,%2,%3};"
        : "+f"(c[0]), "+f"(c[1]), "+f"(c[2]), "+f"(c[3])
        : "r"(a0), "r"(a1), "r"(a2), "r"(a3), "r"(b0), "r"(b1));
}
__device__ __forceinline__ float tanh_fast(float x) {
    float r;
    asm("tanh.approx.f32 %0, %1;" : "=f"(r) : "f"(x));
    return r;
}
__device__ __forceinline__ float sigmoid_fast(float x) {
    return 0.5f * tanh_fast(0.5f * x) + 0.5f;
}
__device__ __forceinline__ float dot4(float4 a, float4 b) {
    return a.x * b.x + a.y * b.y + a.z * b.z + a.w * b.w;
}
__device__ __forceinline__ void grid_barrier(unsigned long long* bar, int nb) {
    __syncthreads();
    __threadfence();
    if (threadIdx.x == 0) {
        unsigned long long old = atomicAdd(bar, 1ull);
        unsigned long long target = (old / nb + 1ull) * (unsigned long long)nb;
        unsigned long long v;
        do {
            asm volatile("ld.global.acquire.gpu.u64 %0, [%1];"
                         : "=l"(v) : "l"(bar));
        } while (v < target);
    }
    __syncthreads();
}

// ---------------- K1: attention partial, T-split x2, 2 chains/warp ----------------
// grid (2, Bv), 512 thr, 2 blocks/SM -> 256 blocks in one wave over 148 SMs.
__global__ void __launch_bounds__(512, 2) k_attn(const float* __restrict__ enc,
                                                 const float* __restrict__ attn_W,
                                                 const float* __restrict__ hidden,
                                                 const float* __restrict__ attn_b,
                                                 float* __restrict__ out) {
    int c = blockIdx.x, b = blockIdx.y;
    int tid = threadIdx.x, w = tid >> 5, lane = tid & 31;
    __shared__ float s_m[16], s_l[16];
    __shared__ __align__(16) float s_ctx[16 * 256];
    __shared__ float s_shred[8];

    float hv = 0.f;
    if (tid < 256) hv = hidden[b * Hv + tid] * attn_W[tid];
#pragma unroll
    for (int o = 16; o; o >>= 1) hv += __shfl_xor_sync(0xffffffffu, hv, o);
    if (lane == 0 && w < 8) s_shred[w] = hv;
    __syncthreads();
    float sh = attn_b[0];
#pragma unroll
    for (int i = 0; i < 8; i++) sh += s_shred[i];

    int h0 = lane * 8;
    float4 we0 = *(const float4*)(attn_W + Hv + h0);
    float4 we1 = *(const float4*)(attn_W + Hv + h0 + 4);
    float wv[8] = {we0.x, we0.y, we0.z, we0.w, we1.x, we1.y, we1.z, we1.w};

    float m[2], l[2], cx[2][8];
#pragma unroll
    for (int j = 0; j < 2; j++) {
        m[j] = NEG_HUGE; l[j] = 0.f;
#pragma unroll
        for (int k = 0; k < 8; k++) cx[j][k] = 0.f;
    }

    const float* base = enc + (size_t)b * Hv + h0;
    const size_t STR = (size_t)Bv * Hv;
    float* rawsc = out + ATTN_OFF + (size_t)b * Tv;
    int tbase = c * 1024;

    float4 P[2][2];
#pragma unroll
    for (int j = 0; j < 2; j++) {
        const float4* p = (const float4*)(base + (size_t)(tbase + w + j * 16) * STR);
        P[j][0] = p[0]; P[j][1] = p[1];
    }

    for (int i = 0; i < 32; i++) {
        float4 C0[2], C1[2];
#pragma unroll
        for (int j = 0; j < 2; j++) { C0[j] = P[j][0]; C1[j] = P[j][1]; }
        if (i < 31) {
            int tb = tbase + (i + 1) * 32 + w;
#pragma unroll
            for (int j = 0; j < 2; j++) {
                const float4* p = (const float4*)(base + (size_t)(tb + j * 16) * STR);
                P[j][0] = p[0]; P[j][1] = p[1];
            }
        }

        float ea[2][8];
#pragma unroll
        for (int j = 0; j < 2; j++) {
            ea[j][0] = C0[j].x; ea[j][1] = C0[j].y; ea[j][2] = C0[j].z; ea[j][3] = C0[j].w;
            ea[j][4] = C1[j].x; ea[j][5] = C1[j].y; ea[j][6] = C1[j].z; ea[j][7] = C1[j].w;
        }

        float s[2];
#pragma unroll
        for (int j = 0; j < 2; j++) {
            float v = 0.f;
#pragma unroll
            for (int k = 0; k < 8; k++) v += ea[j][k] * wv[k];
            s[j] = v;
        }
#pragma unroll
        for (int o = 16; o; o >>= 1) {
#pragma unroll
            for (int j = 0; j < 2; j++)
                s[j] += __shfl_xor_sync(0xffffffffu, s[j], o);
        }
#pragma unroll
        for (int j = 0; j < 2; j++) s[j] += sh;

        if (lane == 0) {
            int t0 = tbase + i * 32 + w;
            rawsc[t0] = s[0];
            rawsc[t0 + 16] = s[1];
        }

#pragma unroll
        for (int j = 0; j < 2; j++) {
            if (s[j] <= m[j]) {
                float p = __expf(s[j] - m[j]);
                l[j] += p;
#pragma unroll
                for (int k = 0; k < 8; k++) cx[j][k] += p * ea[j][k];
            } else {
                float cc = __expf(m[j] - s[j]);
                l[j] = l[j] * cc + 1.f;
#pragma unroll
                for (int k = 0; k < 8; k++) cx[j][k] = cx[j][k] * cc + ea[j][k];
                m[j] = s[j];
            }
        }
    }

    float Mw = fmaxf(m[0], m[1]);
    float e0 = __expf(m[0] - Mw), e1 = __expf(m[1] - Mw);
    float Lw = l[0] * e0 + l[1] * e1;
    s_m[w] = Mw; s_l[w] = Lw;
#pragma unroll
    for (int k = 0; k < 8; k++)
        s_ctx[w * 256 + h0 + k] = cx[0][k] * e0 + cx[1][k] * e1;
    __syncthreads();

    float Mg = NEG_HUGE;
#pragma unroll
    for (int i = 0; i < 16; i++) Mg = fmaxf(Mg, s_m[i]);
    float Lg = 0.f;
#pragma unroll
    for (int i = 0; i < 16; i++) Lg += __expf(s_m[i] - Mg) * s_l[i];

    if (tid == 0) { g_am[c * Bv + b] = Mg; g_al[c * Bv + b] = Lg; }
    if (tid < 256) {
        float acc = 0.f;
#pragma unroll
        for (int i = 0; i < 16; i++) acc += __expf(s_m[i] - Mg) * s_ctx[i * 256 + tid];
        g_actx[(c * Bv + b) * Hv + tid] = acc;   // unnormalized
    }
}

// ---------------- K2: attn-merge -> comb -> gxgh -> gru, grid=128 ----------------
#define CW_STR 516
#define GW_STR 260
#define NBLK 128
__global__ void __launch_bounds__(256) k_mid(const int* __restrict__ tokens,
                                             const float* __restrict__ emb_table,
                                             const float* __restrict__ comb_W,
                                             const float* __restrict__ comb_b,
                                             const float* __restrict__ gru_Wih,
                                             const float* __restrict__ gru_Whh,
                                             const float* __restrict__ bih,
                                             const float* __restrict__ bhh,
                                             const float* __restrict__ hidden,
                                             float* __restrict__ out) {
    extern __shared__ float dsm[];
    int tid = threadIdx.x, bid = blockIdx.x;

    // ---- phase 0: merge attention chunk partials (block = batch row) ----
    {
        int b = bid;
        float m0 = g_am[b],      l0 = g_al[b];
        float m1 = g_am[Bv + b], l1 = g_al[Bv + b];
        float Mg = fmaxf(m0, m1);
        float e0 = __expf(m0 - Mg), e1 = __expf(m1 - Mg);
        float invL = 1.f / (l0 * e0 + l1 * e1);
        if (tid < 256) {
            float acc = g_actx[b * Hv + tid] * e0 + g_actx[(Bv + b) * Hv + tid] * e1;
            out[CTX_OFF + b * Hv + tid] = acc * invL;
        }
        float* rs = out + ATTN_OFF + (size_t)b * Tv;
#pragma unroll
        for (int i = 0; i < 8; i++) {
            int t = i * 256 + tid;
            rs[t] = __expf(rs[t] - Mg) * invL;
        }
    }

    grid_barrier(&g_bar, NBLK);

    // ---- phase 1: comb ----
    if (bid < 64) {
        float* ws = dsm;
        float* xs = dsm + 32 * CW_STR;
        int n0 = (bid & 7) * 32, b0 = (bid >> 3) * 16;
        const float* ctx = out + CTX_OFF;

#pragma unroll
        for (int i = 0; i < 16; i++) {
            int id = i * 256 + tid;
            int r = id >> 7, cc = (id & 127) * 4;
            float4 v = *(const float4*)(comb_W + (size_t)(n0 + r) * 512 + cc);
            *(float4*)(ws + r * CW_STR + cc) = v;
        }
#pragma unroll
        for (int i = 0; i < 8; i++) {
            int id = i * 256 + tid;
            int r = id >> 7, cc = (id & 127) * 4;
            int gb = b0 + r;
            float4 v;
            if (cc < 256) v = *(const float4*)(emb_table + (size_t)tokens[gb] * Hv + cc);
            else          v = *(const float4*)(ctx + (size_t)gb * Hv + (cc - 256));
            *(float4*)(xs + r * 512 + cc) = v;
        }
        __syncthreads();

        int n = tid & 31, bg = tid >> 5;
        const float4* wr = (const float4*)(ws + n * CW_STR);
        const float4* x0 = (const float4*)(xs + (bg * 2 + 0) * 512);
        const float4* x1 = (const float4*)(xs + (bg * 2 + 1) * 512);
        float a0 = 0.f, a1 = 0.f;
#pragma unroll 8
        for (int k4 = 0; k4 < 128; k4++) {
            float4 wv = wr[k4];
            a0 += dot4(wv, x0[k4]);
            a1 += dot4(wv, x1[k4]);
        }
        float bvl = comb_b[n0 + n];
        g_x[(b0 + bg * 2 + 0) * Hv + n0 + n] = fmaxf(a0 + bvl, 0.f);
        g_x[(b0 + bg * 2 + 1) * Hv + n0 + n] = fmaxf(a1 + bvl, 0.f);
    }

    grid_barrier(&g_bar, NBLK);

    // ---- phase 2: gxgh ----
    for (int t = bid; t < 192; t += NBLK) {
        __syncthreads();
        float* ws = dsm;
        float* xs = dsm + 32 * GW_STR;
        int z = t >= 96;
        int rem = t - z * 96;
        int n0 = (rem % 24) * 32, b0 = (rem / 24) * 32;
        const float* A = z ? gru_Whh : gru_Wih;
        const float* B = z ? hidden : g_x;
        const float* bias = z ? bhh : bih;
        float* Y = z ? g_gh : g_gx;

#pragma unroll
        for (int i = 0; i < 8; i++) {
            int id = i * 256 + tid;
            int r = id >> 6, cc = (id & 63) * 4;
            float4 v = *(const float4*)(A + (size_t)(n0 + r) * Hv + cc);
            *(float4*)(ws + r * GW_STR + cc) = v;
        }
#pragma unroll
        for (int i = 0; i < 8; i++) {
            int id = i * 256 + tid;
            int r = id >> 6, cc = (id & 63) * 4;
            float4 v = *(const float4*)(B + (size_t)(b0 + r) * Hv + cc);
            *(float4*)(xs + r * 256 + cc) = v;
        }
        __syncthreads();

        int n = tid & 31, bg = tid >> 5;
        const float4* wr = (const float4*)(ws + n * GW_STR);
        const float4* x0 = (const float4*)(xs + (bg * 4 + 0) * 256);
        const float4* x1 = (const float4*)(xs + (bg * 4 + 1) * 256);
        const float4* x2 = (const float4*)(xs + (bg * 4 + 2) * 256);
        const float4* x3 = (const float4*)(xs + (bg * 4 + 3) * 256);
        float a0 = 0.f, a1 = 0.f, a2 = 0.f, a3 = 0.f;
#pragma unroll 8
        for (int k4 = 0; k4 < 64; k4++) {
            float4 wv = wr[k4];
            a0 += dot4(wv, x0[k4]);
            a1 += dot4(wv, x1[k4]);
            a2 += dot4(wv, x2[k4]);
            a3 += dot4(wv, x3[k4]);
        }
        float bvl = bias[n0 + n];
        Y[(size_t)(b0 + bg * 4 + 0) * 768 + n0 + n] = a0 + bvl;
        Y[(size_t)(b0 + bg * 4 + 1) * 768 + n0 + n] = a1 + bvl;
        Y[(size_t)(b0 + bg * 4 + 2) * 768 + n0 + n] = a2 + bvl;
        Y[(size_t)(b0 + bg * 4 + 3) * 768 + n0 + n] = a3 + bvl;
    }

    grid_barrier(&g_bar, NBLK);

    // ---- phase 3: gru ----
    {
        int b = bid, h = tid;
        float xr = g_gx[b * 768 + h],        hr = g_gh[b * 768 + h];
        float xz = g_gx[b * 768 + 256 + h],  hz = g_gh[b * 768 + 256 + h];
        float xn = g_gx[b * 768 + 512 + h],  hn = g_gh[b * 768 + 512 + h];
        float r = sigmoid_fast(xr + hr);
        float z = sigmoid_fast(xz + hz);
        float n = tanh_fast(xn + r * hn);
        float hprev = hidden[b * Hv + h];
        float hnew = (1.f - z) * n + z * hprev;
        out[HNEW_OFF + b * Hv + h] = hnew;
    }
}

// ---------------- K3: logits GEMM via tf32 mma.sync ----------------
#define SW_STR 36
#define SB_STR 36
#define RES_STR 132
#define SW_SZ  (128 * SW_STR)
#define SB_SZ  (128 * SB_STR)
__global__ void __launch_bounds__(256, 2) k_logits(const float* __restrict__ Wv,
                                                   const float* __restrict__ out_b,
                                                   float* __restrict__ out) {
    __shared__ __align__(16) uint32_t smem[SW_SZ + SB_SZ];
    __shared__ __align__(16) float s_bias[128];
    uint32_t* s_w = smem;
    uint32_t* s_h = smem + SW_SZ;
    float* res = (float*)smem;

    int tid = threadIdx.x, wid = tid >> 5, lane = tid & 31;
    int wm = wid & 3, wn = wid >> 2;
    int vb = blockIdx.x * 128;
    int lr = lane >> 2;
    int lc = lane & 3;
    const float* hB = out + HNEW_OFF;

    if (tid < 128) s_bias[tid] = out_b[vb + tid];

    float acc[2][8][4];
#pragma unroll
    for (int mt = 0; mt < 2; mt++)
#pragma unroll
        for (int j = 0; j < 8; j++)
#pragma unroll
            for (int c = 0; c < 4; c++) acc[mt][j][c] = 0.f;

    for (int kc = 0; kc < 256; kc += 32) {
        __syncthreads();
        {
            int k4 = (tid & 7) * 4;
#pragma unroll
            for (int i = 0; i < 4; i++) {
                int v = (tid >> 3) + i * 32;
                float4 wv = *(const float4*)(Wv + (size_t)(vb + v) * 256 + kc + k4);
                uint32_t* d = s_w + v * SW_STR + k4;
                d[0] = to_tf32(wv.x); d[1] = to_tf32(wv.y);
                d[2] = to_tf32(wv.z); d[3] = to_tf32(wv.w);
            }
        }
        {
            int r = tid >> 1;
            int cbase = (tid & 1) * 16;
#pragma unroll
            for (int i = 0; i < 4; i++) {
                int c = cbase + i * 4;
                float4 hv = *(const float4*)(hB + (size_t)r * 256 + kc + c);
                uint32_t* d = s_h + r * SB_STR + c;
                d[0] = to_tf32(hv.x); d[1] = to_tf32(hv.y);
                d[2] = to_tf32(hv.z); d[3] = to_tf32(hv.w);
            }
        }
        __syncthreads();

#pragma unroll
        for (int ks = 0; ks < 4; ks++) {
            int kk = ks * 8;
            uint32_t af[2][4];
#pragma unroll
            for (int mt = 0; mt < 2; mt++) {
                int row = wm * 32 + mt * 16 + lr;
                af[mt][0] = s_w[row * SW_STR + kk + lc];
                af[mt][1] = s_w[(row + 8) * SW_STR + kk + lc];
                af[mt][2] = s_w[row * SW_STR + kk + 4 + lc];
                af[mt][3] = s_w[(row + 8) * SW_STR + kk + 4 + lc];
            }
            uint32_t bf[8][2];
#pragma unroll
            for (int j = 0; j < 8; j++) {
                int n = wn * 64 + j * 8 + lr;
                bf[j][0] = s_h[n * SB_STR + kk + lc];
                bf[j][1] = s_h[n * SB_STR + kk + 4 + lc];
            }
#pragma unroll
            for (int mt = 0; mt < 2; mt++)
#pragma unroll
                for (int j = 0; j < 8; j++)
                    mma_tf32(acc[mt][j], af[mt][0], af[mt][1], af[mt][2], af[mt][3],
                             bf[j][0], bf[j][1]);
        }
    }

    for (int h = 0; h < 2; h++) {
        __syncthreads();
        if (wn == h) {
#pragma unroll
            for (int mt = 0; mt < 2; mt++)
#pragma unroll
                for (int j = 0; j < 8; j++) {
                    int v0 = wm * 32 + mt * 16 + lr;
                    int b0 = j * 8 + lc * 2;
                    res[(b0    ) * RES_STR + v0    ] = acc[mt][j][0] + s_bias[v0];
                    res[(b0 + 1) * RES_STR + v0    ] = acc[mt][j][1] + s_bias[v0];
                    res[(b0    ) * RES_STR + v0 + 8] = acc[mt][j][2] + s_bias[v0 + 8];
                    res[(b0 + 1) * RES_STR + v0 + 8] = acc[mt][j][3] + s_bias[v0 + 8];
                }
        }
        __syncthreads();
#pragma unroll
        for (int i = 0; i < 32; i++) {
            int idx = i * 256 + tid;
            int bb = idx >> 7, v = idx & 127;
            out[(size_t)(h * 64 + bb) * Vv + vb + v] = res[bb * RES_STR + v];
        }
#pragma unroll
        for (int rr = 0; rr < 8; rr++) {
            int r = wid * 8 + rr;
            float4 x = *(const float4*)&res[r * RES_STR + lane * 4];
            float mx = fmaxf(fmaxf(x.x, x.y), fmaxf(x.z, x.w));
#pragma unroll
            for (int o = 16; o; o >>= 1) mx = fmaxf(mx, __shfl_xor_sync(0xffffffffu, mx, o));
            float se = __expf(x.x - mx) + __expf(x.y - mx) + __expf(x.z - mx) + __expf(x.w - mx);
#pragma unroll
            for (int o = 16; o; o >>= 1) se += __shfl_xor_sync(0xffffffffu, se, o);
            if (lane == 0) {
                int gb = h * 64 + r;
                g_pmax[gb * NTILES + blockIdx.x] = mx;
                g_psum[gb * NTILES + blockIdx.x] = se;
            }
        }
    }
}

// ---------------- K4: fused lse + subtract, segment prefetched ----------------
__global__ void __launch_bounds__(256) k_tail(float* __restrict__ out) {
    int b = blockIdx.x, y = blockIdx.y;
    int tid = threadIdx.x, wid = tid >> 5, lane = tid & 31;
    __shared__ float s_rm[8], s_rl[8];

    // prefetch this block's segment (<=4 float4/thread) BEFORE the reduce
    float4* row = (float4*)(out + (size_t)b * Vv) + y * 1000;
    float4 xv[4];
    int nv = 0;
#pragma unroll
    for (int i = 0; i < 4; i++) {
        int v = i * 256 + tid;
        if (v < 1000) { xv[i] = row[v]; nv = i + 1; }
    }

    // coalesced reduce of 250 partials for row b
    float m = NEG_HUGE, l = 0.f;
    if (tid < NTILES) {
        m = g_pmax[b * NTILES + tid];
        l = g_psum[b * NTILES + tid];
    }
#pragma unroll
    for (int o = 16; o; o >>= 1) {
        float m2 = __shfl_xor_sync(0xffffffffu, m, o);
        float l2 = __shfl_xor_sync(0xffffffffu, l, o);
        float nm = fmaxf(m, m2);
        l = l * __expf(m - nm) + l2 * __expf(m2 - nm);
        m = nm;
    }
    if (lane == 0) { s_rm[wid] = m; s_rl[wid] = l; }
    __syncthreads();
    float M = NEG_HUGE;
#pragma unroll
    for (int i = 0; i < 8; i++) M = fmaxf(M, s_rm[i]);
    float L = 0.f;
#pragma unroll
    for (int i = 0; i < 8; i++) L += s_rl[i] * __expf(s_rm[i] - M);
    float lse = M + logf(L);

#pragma unroll
    for (int i = 0; i < 4; i++) {
        int v = i * 256 + tid;
        if (i < nv) {
            float4 x = xv[i];
            x.x -= lse; x.y -= lse; x.z -= lse; x.w -= lse;
            row[v] = x;
        }
    }
}

// ---------------- launch ----------------
extern "C" void kernel_launch(void* const* d_in, const int* in_sizes, int n_in,
                              void* d_out, int out_size) {
    const int*   tokens    = (const int*)d_in[0];
    const float* hidden    = (const float*)d_in[1];
    const float* enc       = (const float*)d_in[2];
    const float* emb_table = (const float*)d_in[3];
    const float* attn_W    = (const float*)d_in[4];
    const float* attn_b    = (const float*)d_in[5];
    const float* comb_W    = (const float*)d_in[6];
    const float* comb_b    = (const float*)d_in[7];
    const float* gru_Wih   = (const float*)d_in[8];
    const float* gru_Whh   = (const float*)d_in[9];
    const float* gru_bih   = (const float*)d_in[10];
    const float* gru_bhh   = (const float*)d_in[11];
    const float* out_W     = (const float*)d_in[12];
    const float* out_b     = (const float*)d_in[13];
    float* out = (float*)d_out;

    const int M_SMEM = (32 * CW_STR + 16 * 512) * 4;   // 98,816 B
    cudaFuncSetAttribute(k_mid, cudaFuncAttributeMaxDynamicSharedMemorySize, M_SMEM);

    k_attn<<<dim3(2, Bv), 512>>>(enc, attn_W, hidden, attn_b, out);
    k_mid<<<NBLK, 256, M_SMEM>>>(tokens, emb_table, comb_W, comb_b,
                                 gru_Wih, gru_Whh, gru_bih, gru_bhh, hidden, out);
    k_logits<<<NTILES, 256>>>(out_W, out_b, out);
    k_tail<<<dim3(Bv, 8), 256>>>(out);
}

// round 13
// speedup vs baseline: 1.1271x; 1.1271x over previous
#include <cuda_runtime.h>
#include <cuda_bf16.h>
#include <cstdint>

#define Bv   128
#define Hv   256
#define Tv   2048
#define Vv   32000
#define NTILES 250            // Vv / 128

#define LOGP_OFF  0
#define HNEW_OFF  (Bv*Vv)                 // 4,096,000
#define ATTN_OFF  (HNEW_OFF + Bv*Hv)      // 4,128,768
#define CTX_OFF   (ATTN_OFF + Bv*Tv)      // 4,390,912

#define NEG_HUGE  (-3.402823466e38f)

// ---------------- scratch ----------------
__device__ __align__(16) float g_x[Bv * Hv];       // relu(comb) [b][n]
__device__ __align__(16) float g_gx[Bv * 3 * Hv];
__device__ __align__(16) float g_gh[Bv * 3 * Hv];
__device__ __align__(16) float g_pmax[Bv * NTILES];  // [b][tile] coalesced
__device__ __align__(16) float g_psum[Bv * NTILES];
__device__ unsigned long long g_bar = 0ull;        // k_mid barrier (nb=128)

// ---------------- helpers ----------------
__device__ __forceinline__ uint32_t to_tf32(float x) {
    uint32_t r;
    asm("cvt.rna.tf32.f32 %0, %1;" : "=r"(r) : "f"(x));
    return r;
}
__device__ __forceinline__ void mma_tf32(float* c, uint32_t a0, uint32_t a1,
                                         uint32_t a2, uint32_t a3,
                                         uint32_t b0, uint32_t b1) {
    asm("mma.sync.aligned.m16n8k8.row.col.f32.tf32.tf32.f32 "
        "{%0,%1,%2,%3},{%4,%5,%6,%7},{%8,%9},{%0,%1,%2,%3};"
        : "+f"(c[0]), "+f"(c[1]), "+f"(c[2]), "+f"(c[3])
        : "r"(a0), "r"(a1), "r"(a2), "r"(a3), "r"(b0), "r"(b1));
}
__device__ __forceinline__ float tanh_fast(float x) {
    float r;
    asm("tanh.approx.f32 %0, %1;" : "=f"(r) : "f"(x));
    return r;
}
__device__ __forceinline__ float sigmoid_fast(float x) {
    return 0.5f * tanh_fast(0.5f * x) + 0.5f;
}
__device__ __forceinline__ float dot4(float4 a, float4 b) {
    return a.x * b.x + a.y * b.y + a.z * b.z + a.w * b.w;
}
__device__ __forceinline__ uint32_t sptr(const void* p) {
    uint32_t r;
    asm("{ .reg .u64 t; cvta.to.shared.u64 t, %1; cvt.u32.u64 %0, t; }"
        : "=r"(r) : "l"(p));
    return r;
}
__device__ __forceinline__ void cp16(float* smem_dst, const float* gsrc) {
    asm volatile("cp.async.cg.shared.global [%0], [%1], 16;"
                 :: "r"(sptr(smem_dst)), "l"(gsrc));
}
#define CP_COMMIT() asm volatile("cp.async.commit_group;")
template <int N>
__device__ __forceinline__ void cp_wait() {
    asm volatile("cp.async.wait_group %0;" :: "n"(N));
}
__device__ __forceinline__ void grid_barrier(unsigned long long* bar, int nb) {
    __syncthreads();
    __threadfence();
    if (threadIdx.x == 0) {
        unsigned long long old = atomicAdd(bar, 1ull);
        unsigned long long target = (old / nb + 1ull) * (unsigned long long)nb;
        unsigned long long v;
        do {
            asm volatile("ld.global.acquire.gpu.u64 %0, [%1];"
                         : "=l"(v) : "l"(bar));
        } while (v < target);
    }
    __syncthreads();
}

// ---------------- K1: fused attention (R11-proven: single pass, 4 chains/warp) ----------------
__global__ void __launch_bounds__(512) k_attn(const float* __restrict__ enc,
                                              const float* __restrict__ attn_W,
                                              const float* __restrict__ hidden,
                                              const float* __restrict__ attn_b,
                                              float* __restrict__ out) {
    int b = blockIdx.x;
    int tid = threadIdx.x, w = tid >> 5, lane = tid & 31;
    __shared__ float s_scores[Tv];
    __shared__ float s_m[16], s_l[16];
    __shared__ __align__(16) float s_ctx[16 * 256];
    __shared__ float s_shred[8];

    float hv = 0.f;
    if (tid < 256) hv = hidden[b * Hv + tid] * attn_W[tid];
#pragma unroll
    for (int o = 16; o; o >>= 1) hv += __shfl_xor_sync(0xffffffffu, hv, o);
    if (lane == 0 && w < 8) s_shred[w] = hv;
    __syncthreads();
    float sh = attn_b[0];
#pragma unroll
    for (int i = 0; i < 8; i++) sh += s_shred[i];

    int h0 = lane * 8;
    float4 we0 = *(const float4*)(attn_W + Hv + h0);
    float4 we1 = *(const float4*)(attn_W + Hv + h0 + 4);
    float wv[8] = {we0.x, we0.y, we0.z, we0.w, we1.x, we1.y, we1.z, we1.w};

    float m[4], l[4], c[4][8];
#pragma unroll
    for (int j = 0; j < 4; j++) {
        m[j] = NEG_HUGE; l[j] = 0.f;
#pragma unroll
        for (int k = 0; k < 8; k++) c[j][k] = 0.f;
    }

    const float* base = enc + (size_t)b * Hv + h0;
    const size_t STR = (size_t)Bv * Hv;

    float4 P[4][2];
#pragma unroll
    for (int j = 0; j < 4; j++) {
        const float4* p = (const float4*)(base + (size_t)(w + j * 16) * STR);
        P[j][0] = p[0]; P[j][1] = p[1];
    }

    for (int i = 0; i < 32; i++) {
        float4 C0[4], C1[4];
#pragma unroll
        for (int j = 0; j < 4; j++) { C0[j] = P[j][0]; C1[j] = P[j][1]; }
        if (i < 31) {
            int tb = (i + 1) * 64 + w;
#pragma unroll
            for (int j = 0; j < 4; j++) {
                const float4* p = (const float4*)(base + (size_t)(tb + j * 16) * STR);
                P[j][0] = p[0]; P[j][1] = p[1];
            }
        }

        float ea[4][8];
#pragma unroll
        for (int j = 0; j < 4; j++) {
            ea[j][0] = C0[j].x; ea[j][1] = C0[j].y; ea[j][2] = C0[j].z; ea[j][3] = C0[j].w;
            ea[j][4] = C1[j].x; ea[j][5] = C1[j].y; ea[j][6] = C1[j].z; ea[j][7] = C1[j].w;
        }

        float s[4];
#pragma unroll
        for (int j = 0; j < 4; j++) {
            float v = 0.f;
#pragma unroll
            for (int k = 0; k < 8; k++) v += ea[j][k] * wv[k];
            s[j] = v;
        }
#pragma unroll
        for (int o = 16; o; o >>= 1) {
#pragma unroll
            for (int j = 0; j < 4; j++)
                s[j] += __shfl_xor_sync(0xffffffffu, s[j], o);
        }
#pragma unroll
        for (int j = 0; j < 4; j++) s[j] += sh;

        if (lane == 0) {
            int t0 = i * 64 + w;
#pragma unroll
            for (int j = 0; j < 4; j++) s_scores[t0 + j * 16] = s[j];
        }

#pragma unroll
        for (int j = 0; j < 4; j++) {
            if (s[j] <= m[j]) {
                float p = __expf(s[j] - m[j]);
                l[j] += p;
#pragma unroll
                for (int k = 0; k < 8; k++) c[j][k] += p * ea[j][k];
            } else {
                float cc = __expf(m[j] - s[j]);
                l[j] = l[j] * cc + 1.f;
#pragma unroll
                for (int k = 0; k < 8; k++) c[j][k] = c[j][k] * cc + ea[j][k];
                m[j] = s[j];
            }
        }
    }

    float Mw = fmaxf(fmaxf(m[0], m[1]), fmaxf(m[2], m[3]));
    float e[4];
#pragma unroll
    for (int j = 0; j < 4; j++) e[j] = __expf(m[j] - Mw);
    float Lw = l[0] * e[0] + l[1] * e[1] + l[2] * e[2] + l[3] * e[3];
    s_m[w] = Mw; s_l[w] = Lw;
#pragma unroll
    for (int k = 0; k < 8; k++)
        s_ctx[w * 256 + h0 + k] = c[0][k] * e[0] + c[1][k] * e[1]
                                + c[2][k] * e[2] + c[3][k] * e[3];
    __syncthreads();

    float Mg = NEG_HUGE;
#pragma unroll
    for (int i = 0; i < 16; i++) Mg = fmaxf(Mg, s_m[i]);
    float Lg = 0.f;
#pragma unroll
    for (int i = 0; i < 16; i++) Lg += __expf(s_m[i] - Mg) * s_l[i];
    float invL = 1.f / Lg;

    if (tid < 256) {
        float acc = 0.f;
#pragma unroll
        for (int i = 0; i < 16; i++) acc += __expf(s_m[i] - Mg) * s_ctx[i * 256 + tid];
        acc *= invL;
        out[CTX_OFF + b * Hv + tid] = acc;
    }
    for (int t = tid; t < Tv; t += 512)
        out[ATTN_OFF + (size_t)b * Tv + t] = __expf(s_scores[t] - Mg) * invL;
}

// ---------------- K2: fused comb -> gxgh -> gru, one kernel, grid=128 ----------------
#define CW_STR 516
#define GW_STR 260
#define NBLK 128
__global__ void __launch_bounds__(256) k_mid(const int* __restrict__ tokens,
                                             const float* __restrict__ emb_table,
                                             const float* __restrict__ comb_W,
                                             const float* __restrict__ comb_b,
                                             const float* __restrict__ gru_Wih,
                                             const float* __restrict__ gru_Whh,
                                             const float* __restrict__ bih,
                                             const float* __restrict__ bhh,
                                             const float* __restrict__ hidden,
                                             float* __restrict__ out) {
    extern __shared__ float dsm[];
    int tid = threadIdx.x, bid = blockIdx.x;

    // ---- phase 1: comb ----
    if (bid < 64) {
        float* ws = dsm;
        float* xs = dsm + 32 * CW_STR;
        int n0 = (bid & 7) * 32, b0 = (bid >> 3) * 16;
        const float* ctx = out + CTX_OFF;

#pragma unroll
        for (int i = 0; i < 16; i++) {
            int id = i * 256 + tid;
            int r = id >> 7, cc = (id & 127) * 4;
            float4 v = *(const float4*)(comb_W + (size_t)(n0 + r) * 512 + cc);
            *(float4*)(ws + r * CW_STR + cc) = v;
        }
#pragma unroll
        for (int i = 0; i < 8; i++) {
            int id = i * 256 + tid;
            int r = id >> 7, cc = (id & 127) * 4;
            int gb = b0 + r;
            float4 v;
            if (cc < 256) v = *(const float4*)(emb_table + (size_t)tokens[gb] * Hv + cc);
            else          v = *(const float4*)(ctx + (size_t)gb * Hv + (cc - 256));
            *(float4*)(xs + r * 512 + cc) = v;
        }
        __syncthreads();

        int n = tid & 31, bg = tid >> 5;
        const float4* wr = (const float4*)(ws + n * CW_STR);
        const float4* x0 = (const float4*)(xs + (bg * 2 + 0) * 512);
        const float4* x1 = (const float4*)(xs + (bg * 2 + 1) * 512);
        float a0 = 0.f, a1 = 0.f;
#pragma unroll 8
        for (int k4 = 0; k4 < 128; k4++) {
            float4 wv = wr[k4];
            a0 += dot4(wv, x0[k4]);
            a1 += dot4(wv, x1[k4]);
        }
        float bvl = comb_b[n0 + n];
        g_x[(b0 + bg * 2 + 0) * Hv + n0 + n] = fmaxf(a0 + bvl, 0.f);
        g_x[(b0 + bg * 2 + 1) * Hv + n0 + n] = fmaxf(a1 + bvl, 0.f);
    }

    grid_barrier(&g_bar, NBLK);

    // ---- phase 2: gxgh ----
    for (int t = bid; t < 192; t += NBLK) {
        __syncthreads();
        float* ws = dsm;
        float* xs = dsm + 32 * GW_STR;
        int z = t >= 96;
        int rem = t - z * 96;
        int n0 = (rem % 24) * 32, b0 = (rem / 24) * 32;
        const float* A = z ? gru_Whh : gru_Wih;
        const float* B = z ? hidden : g_x;
        const float* bias = z ? bhh : bih;
        float* Y = z ? g_gh : g_gx;

#pragma unroll
        for (int i = 0; i < 8; i++) {
            int id = i * 256 + tid;
            int r = id >> 6, cc = (id & 63) * 4;
            float4 v = *(const float4*)(A + (size_t)(n0 + r) * Hv + cc);
            *(float4*)(ws + r * GW_STR + cc) = v;
        }
#pragma unroll
        for (int i = 0; i < 8; i++) {
            int id = i * 256 + tid;
            int r = id >> 6, cc = (id & 63) * 4;
            float4 v = *(const float4*)(B + (size_t)(b0 + r) * Hv + cc);
            *(float4*)(xs + r * 256 + cc) = v;
        }
        __syncthreads();

        int n = tid & 31, bg = tid >> 5;
        const float4* wr = (const float4*)(ws + n * GW_STR);
        const float4* x0 = (const float4*)(xs + (bg * 4 + 0) * 256);
        const float4* x1 = (const float4*)(xs + (bg * 4 + 1) * 256);
        const float4* x2 = (const float4*)(xs + (bg * 4 + 2) * 256);
        const float4* x3 = (const float4*)(xs + (bg * 4 + 3) * 256);
        float a0 = 0.f, a1 = 0.f, a2 = 0.f, a3 = 0.f;
#pragma unroll 8
        for (int k4 = 0; k4 < 64; k4++) {
            float4 wv = wr[k4];
            a0 += dot4(wv, x0[k4]);
            a1 += dot4(wv, x1[k4]);
            a2 += dot4(wv, x2[k4]);
            a3 += dot4(wv, x3[k4]);
        }
        float bvl = bias[n0 + n];
        Y[(size_t)(b0 + bg * 4 + 0) * 768 + n0 + n] = a0 + bvl;
        Y[(size_t)(b0 + bg * 4 + 1) * 768 + n0 + n] = a1 + bvl;
        Y[(size_t)(b0 + bg * 4 + 2) * 768 + n0 + n] = a2 + bvl;
        Y[(size_t)(b0 + bg * 4 + 3) * 768 + n0 + n] = a3 + bvl;
    }

    grid_barrier(&g_bar, NBLK);

    // ---- phase 3: gru ----
    {
        int b = bid, h = tid;
        float xr = g_gx[b * 768 + h],        hr = g_gh[b * 768 + h];
        float xz = g_gx[b * 768 + 256 + h],  hz = g_gh[b * 768 + 256 + h];
        float xn = g_gx[b * 768 + 512 + h],  hn = g_gh[b * 768 + 512 + h];
        float r = sigmoid_fast(xr + hr);
        float z = sigmoid_fast(xz + hz);
        float n = tanh_fast(xn + r * hn);
        float hprev = hidden[b * Hv + h];
        float hnew = (1.f - z) * n + z * hprev;
        out[HNEW_OFF + b * Hv + h] = hnew;
    }
}

// ---------------- K3: logits GEMM, tf32 mma + cp.async double buffer ----------------
#define LG_STR 36
#define LG_STAGE (2 * 128 * LG_STR)       // W + B per stage, floats
__global__ void __launch_bounds__(256, 2) k_logits(const float* __restrict__ Wv,
                                                   const float* __restrict__ out_b,
                                                   float* __restrict__ out) {
    extern __shared__ float dsm[];
    __shared__ __align__(16) float s_bias[128];
    float* res = dsm;   // epilogue reuse: 64 * 132 floats

    int tid = threadIdx.x, wid = tid >> 5, lane = tid & 31;
    int wm = wid & 3, wn = wid >> 2;
    int vb = blockIdx.x * 128;
    int lr = lane >> 2;
    int lc = lane & 3;
    const float* hB = out + HNEW_OFF;

    if (tid < 128) s_bias[tid] = out_b[vb + tid];

    float acc[2][8][4];
#pragma unroll
    for (int mt = 0; mt < 2; mt++)
#pragma unroll
        for (int j = 0; j < 8; j++)
#pragma unroll
            for (int c = 0; c < 4; c++) acc[mt][j][c] = 0.f;

    auto load_chunk = [&](int c, int s) {
        int kc = c * 32;
        float* sW = dsm + s * LG_STAGE;
        float* sB = sW + 128 * LG_STR;
        int r = tid >> 1, u0 = (tid & 1) * 4;
#pragma unroll
        for (int i = 0; i < 4; i++) {
            int u = u0 + i;
            cp16(sW + r * LG_STR + u * 4, Wv + (size_t)(vb + r) * 256 + kc + u * 4);
            cp16(sB + r * LG_STR + u * 4, hB + (size_t)r * 256 + kc + u * 4);
        }
    };
    auto compute = [&](int s) {
        float* sW = dsm + s * LG_STAGE;
        float* sB = sW + 128 * LG_STR;
#pragma unroll
        for (int ks = 0; ks < 4; ks++) {
            int kk = ks * 8;
            uint32_t af[2][4];
#pragma unroll
            for (int mt = 0; mt < 2; mt++) {
                int row = wm * 32 + mt * 16 + lr;
                af[mt][0] = to_tf32(sW[row * LG_STR + kk + lc]);
                af[mt][1] = to_tf32(sW[(row + 8) * LG_STR + kk + lc]);
                af[mt][2] = to_tf32(sW[row * LG_STR + kk + 4 + lc]);
                af[mt][3] = to_tf32(sW[(row + 8) * LG_STR + kk + 4 + lc]);
            }
            uint32_t bf[8][2];
#pragma unroll
            for (int j = 0; j < 8; j++) {
                int n = wn * 64 + j * 8 + lr;
                bf[j][0] = to_tf32(sB[n * LG_STR + kk + lc]);
                bf[j][1] = to_tf32(sB[n * LG_STR + kk + 4 + lc]);
            }
#pragma unroll
            for (int mt = 0; mt < 2; mt++)
#pragma unroll
                for (int j = 0; j < 8; j++)
                    mma_tf32(acc[mt][j], af[mt][0], af[mt][1], af[mt][2], af[mt][3],
                             bf[j][0], bf[j][1]);
        }
    };

    load_chunk(0, 0); CP_COMMIT();
    for (int c = 0; c < 8; c++) {
        if (c < 7) { load_chunk(c + 1, (c + 1) & 1); CP_COMMIT(); cp_wait<1>(); }
        else cp_wait<0>();
        __syncthreads();
        compute(c & 1);
        __syncthreads();
    }

    // epilogue: two b-halves of 64 staged in smem (bias folded), write + partials
    for (int h = 0; h < 2; h++) {
        __syncthreads();
        if (wn == h) {
#pragma unroll
            for (int mt = 0; mt < 2; mt++)
#pragma unroll
                for (int j = 0; j < 8; j++) {
                    int v0 = wm * 32 + mt * 16 + lr;
                    int b0 = j * 8 + lc * 2;
                    res[(b0    ) * 132 + v0    ] = acc[mt][j][0] + s_bias[v0];
                    res[(b0 + 1) * 132 + v0    ] = acc[mt][j][1] + s_bias[v0];
                    res[(b0    ) * 132 + v0 + 8] = acc[mt][j][2] + s_bias[v0 + 8];
                    res[(b0 + 1) * 132 + v0 + 8] = acc[mt][j][3] + s_bias[v0 + 8];
                }
        }
        __syncthreads();
#pragma unroll
        for (int i = 0; i < 32; i++) {
            int idx = i * 256 + tid;
            int bb = idx >> 7, v = idx & 127;
            out[(size_t)(h * 64 + bb) * Vv + vb + v] = res[bb * 132 + v];
        }
#pragma unroll
        for (int rr = 0; rr < 8; rr++) {
            int r = wid * 8 + rr;
            float4 x = *(const float4*)&res[r * 132 + lane * 4];
            float mx = fmaxf(fmaxf(x.x, x.y), fmaxf(x.z, x.w));
#pragma unroll
            for (int o = 16; o; o >>= 1) mx = fmaxf(mx, __shfl_xor_sync(0xffffffffu, mx, o));
            float se = __expf(x.x - mx) + __expf(x.y - mx) + __expf(x.z - mx) + __expf(x.w - mx);
#pragma unroll
            for (int o = 16; o; o >>= 1) se += __shfl_xor_sync(0xffffffffu, se, o);
            if (lane == 0) {
                int gb = h * 64 + r;
                g_pmax[gb * NTILES + blockIdx.x] = mx;
                g_psum[gb * NTILES + blockIdx.x] = se;
            }
        }
    }
}

// ---------------- K4: fused lse + subtract, segment prefetched ----------------
__global__ void __launch_bounds__(256) k_tail(float* __restrict__ out) {
    int b = blockIdx.x, y = blockIdx.y;
    int tid = threadIdx.x, wid = tid >> 5, lane = tid & 31;
    __shared__ float s_rm[8], s_rl[8];

    float4* row = (float4*)(out + (size_t)b * Vv) + y * 1000;
    float4 xv[4];
    int nv = 0;
#pragma unroll
    for (int i = 0; i < 4; i++) {
        int v = i * 256 + tid;
        if (v < 1000) { xv[i] = row[v]; nv = i + 1; }
    }

    float m = NEG_HUGE, l = 0.f;
    if (tid < NTILES) {
        m = g_pmax[b * NTILES + tid];
        l = g_psum[b * NTILES + tid];
    }
#pragma unroll
    for (int o = 16; o; o >>= 1) {
        float m2 = __shfl_xor_sync(0xffffffffu, m, o);
        float l2 = __shfl_xor_sync(0xffffffffu, l, o);
        float nm = fmaxf(m, m2);
        l = l * __expf(m - nm) + l2 * __expf(m2 - nm);
        m = nm;
    }
    if (lane == 0) { s_rm[wid] = m; s_rl[wid] = l; }
    __syncthreads();
    float M = NEG_HUGE;
#pragma unroll
    for (int i = 0; i < 8; i++) M = fmaxf(M, s_rm[i]);
    float L = 0.f;
#pragma unroll
    for (int i = 0; i < 8; i++) L += s_rl[i] * __expf(s_rm[i] - M);
    float lse = M + logf(L);

#pragma unroll
    for (int i = 0; i < 4; i++) {
        int v = i * 256 + tid;
        if (i < nv) {
            float4 x = xv[i];
            x.x -= lse; x.y -= lse; x.z -= lse; x.w -= lse;
            row[v] = x;
        }
    }
}

// ---------------- launch ----------------
extern "C" void kernel_launch(void* const* d_in, const int* in_sizes, int n_in,
                              void* d_out, int out_size) {
    const int*   tokens    = (const int*)d_in[0];
    const float* hidden    = (const float*)d_in[1];
    const float* enc       = (const float*)d_in[2];
    const float* emb_table = (const float*)d_in[3];
    const float* attn_W    = (const float*)d_in[4];
    const float* attn_b    = (const float*)d_in[5];
    const float* comb_W    = (const float*)d_in[6];
    const float* comb_b    = (const float*)d_in[7];
    const float* gru_Wih   = (const float*)d_in[8];
    const float* gru_Whh   = (const float*)d_in[9];
    const float* gru_bih   = (const float*)d_in[10];
    const float* gru_bhh   = (const float*)d_in[11];
    const float* out_W     = (const float*)d_in[12];
    const float* out_b     = (const float*)d_in[13];
    float* out = (float*)d_out;

    const int M_SMEM = (32 * CW_STR + 16 * 512) * 4;   // 98,816 B
    const int L_SMEM = 2 * LG_STAGE * 4;               // 73,728 B
    cudaFuncSetAttribute(k_mid,    cudaFuncAttributeMaxDynamicSharedMemorySize, M_SMEM);
    cudaFuncSetAttribute(k_logits, cudaFuncAttributeMaxDynamicSharedMemorySize, L_SMEM);

    k_attn<<<Bv, 512>>>(enc, attn_W, hidden, attn_b, out);
    k_mid<<<NBLK, 256, M_SMEM>>>(tokens, emb_table, comb_W, comb_b,
                                 gru_Wih, gru_Whh, gru_bih, gru_bhh, hidden, out);
    k_logits<<<NTILES, 256, L_SMEM>>>(out_W, out_b, out);
    k_tail<<<dim3(Bv, 8), 256>>>(out);
}

// round 14
// speedup vs baseline: 1.1685x; 1.0368x over previous
#include <cuda_runtime.h>
#include <cuda_bf16.h>
#include <cstdint>

#define Bv   128
#define Hv   256
#define Tv   2048
#define Vv   32000
#define NTILES 250            // Vv / 128

#define LOGP_OFF  0
#define HNEW_OFF  (Bv*Vv)                 // 4,096,000
#define ATTN_OFF  (HNEW_OFF + Bv*Hv)      // 4,128,768
#define CTX_OFF   (ATTN_OFF + Bv*Tv)      // 4,390,912

#define NEG_HUGE  (-3.402823466e38f)

// ---------------- scratch ----------------
__device__ __align__(16) float g_x[Bv * Hv];       // relu(comb) [b][n]
__device__ __align__(16) float g_gx[Bv * 3 * Hv];
__device__ __align__(16) float g_gh[Bv * 3 * Hv];
__device__ __align__(16) float g_pmax[Bv * NTILES];  // [b][tile] coalesced
__device__ __align__(16) float g_psum[Bv * NTILES];
__device__ unsigned long long g_bar = 0ull;        // k_mid barrier (nb=128)

// ---------------- helpers ----------------
__device__ __forceinline__ uint32_t to_tf32(float x) {
    uint32_t r;
    asm("cvt.rna.tf32.f32 %0, %1;" : "=r"(r) : "f"(x));
    return r;
}
__device__ __forceinline__ void mma_tf32(float* c, uint32_t a0, uint32_t a1,
                                         uint32_t a2, uint32_t a3,
                                         uint32_t b0, uint32_t b1) {
    asm("mma.sync.aligned.m16n8k8.row.col.f32.tf32.tf32.f32 "
        "{%0,%1,%2,%3},{%4,%5,%6,%7},{%8,%9},{%0,%1,%2,%3};"
        : "+f"(c[0]), "+f"(c[1]), "+f"(c[2]), "+f"(c[3])
        : "r"(a0), "r"(a1), "r"(a2), "r"(a3), "r"(b0), "r"(b1));
}
__device__ __forceinline__ float tanh_fast(float x) {
    float r;
    asm("tanh.approx.f32 %0, %1;" : "=f"(r) : "f"(x));
    return r;
}
__device__ __forceinline__ float sigmoid_fast(float x) {
    return 0.5f * tanh_fast(0.5f * x) + 0.5f;
}
__device__ __forceinline__ float dot4(float4 a, float4 b) {
    return a.x * b.x + a.y * b.y + a.z * b.z + a.w * b.w;
}
__device__ __forceinline__ void grid_barrier(unsigned long long* bar, int nb) {
    __syncthreads();
    __threadfence();
    if (threadIdx.x == 0) {
        unsigned long long old = atomicAdd(bar, 1ull);
        unsigned long long target = (old / nb + 1ull) * (unsigned long long)nb;
        unsigned long long v;
        do {
            asm volatile("ld.global.acquire.gpu.u64 %0, [%1];"
                         : "=l"(v) : "l"(bar));
        } while (v < target);
    }
    __syncthreads();
}

// ---------------- K1: fused attention (R11-proven: single pass, 4 chains/warp) ----------------
__global__ void __launch_bounds__(512) k_attn(const float* __restrict__ enc,
                                              const float* __restrict__ attn_W,
                                              const float* __restrict__ hidden,
                                              const float* __restrict__ attn_b,
                                              float* __restrict__ out) {
    int b = blockIdx.x;
    int tid = threadIdx.x, w = tid >> 5, lane = tid & 31;
    __shared__ float s_scores[Tv];
    __shared__ float s_m[16], s_l[16];
    __shared__ __align__(16) float s_ctx[16 * 256];
    __shared__ float s_shred[8];

    float hv = 0.f;
    if (tid < 256) hv = hidden[b * Hv + tid] * attn_W[tid];
#pragma unroll
    for (int o = 16; o; o >>= 1) hv += __shfl_xor_sync(0xffffffffu, hv, o);
    if (lane == 0 && w < 8) s_shred[w] = hv;
    __syncthreads();
    float sh = attn_b[0];
#pragma unroll
    for (int i = 0; i < 8; i++) sh += s_shred[i];

    int h0 = lane * 8;
    float4 we0 = *(const float4*)(attn_W + Hv + h0);
    float4 we1 = *(const float4*)(attn_W + Hv + h0 + 4);
    float wv[8] = {we0.x, we0.y, we0.z, we0.w, we1.x, we1.y, we1.z, we1.w};

    float m[4], l[4], c[4][8];
#pragma unroll
    for (int j = 0; j < 4; j++) {
        m[j] = NEG_HUGE; l[j] = 0.f;
#pragma unroll
        for (int k = 0; k < 8; k++) c[j][k] = 0.f;
    }

    const float* base = enc + (size_t)b * Hv + h0;
    const size_t STR = (size_t)Bv * Hv;

    float4 P[4][2];
#pragma unroll
    for (int j = 0; j < 4; j++) {
        const float4* p = (const float4*)(base + (size_t)(w + j * 16) * STR);
        P[j][0] = p[0]; P[j][1] = p[1];
    }

    for (int i = 0; i < 32; i++) {
        float4 C0[4], C1[4];
#pragma unroll
        for (int j = 0; j < 4; j++) { C0[j] = P[j][0]; C1[j] = P[j][1]; }
        if (i < 31) {
            int tb = (i + 1) * 64 + w;
#pragma unroll
            for (int j = 0; j < 4; j++) {
                const float4* p = (const float4*)(base + (size_t)(tb + j * 16) * STR);
                P[j][0] = p[0]; P[j][1] = p[1];
            }
        }

        float ea[4][8];
#pragma unroll
        for (int j = 0; j < 4; j++) {
            ea[j][0] = C0[j].x; ea[j][1] = C0[j].y; ea[j][2] = C0[j].z; ea[j][3] = C0[j].w;
            ea[j][4] = C1[j].x; ea[j][5] = C1[j].y; ea[j][6] = C1[j].z; ea[j][7] = C1[j].w;
        }

        float s[4];
#pragma unroll
        for (int j = 0; j < 4; j++) {
            float v = 0.f;
#pragma unroll
            for (int k = 0; k < 8; k++) v += ea[j][k] * wv[k];
            s[j] = v;
        }
#pragma unroll
        for (int o = 16; o; o >>= 1) {
#pragma unroll
            for (int j = 0; j < 4; j++)
                s[j] += __shfl_xor_sync(0xffffffffu, s[j], o);
        }
#pragma unroll
        for (int j = 0; j < 4; j++) s[j] += sh;

        if (lane == 0) {
            int t0 = i * 64 + w;
#pragma unroll
            for (int j = 0; j < 4; j++) s_scores[t0 + j * 16] = s[j];
        }

#pragma unroll
        for (int j = 0; j < 4; j++) {
            if (s[j] <= m[j]) {
                float p = __expf(s[j] - m[j]);
                l[j] += p;
#pragma unroll
                for (int k = 0; k < 8; k++) c[j][k] += p * ea[j][k];
            } else {
                float cc = __expf(m[j] - s[j]);
                l[j] = l[j] * cc + 1.f;
#pragma unroll
                for (int k = 0; k < 8; k++) c[j][k] = c[j][k] * cc + ea[j][k];
                m[j] = s[j];
            }
        }
    }

    float Mw = fmaxf(fmaxf(m[0], m[1]), fmaxf(m[2], m[3]));
    float e[4];
#pragma unroll
    for (int j = 0; j < 4; j++) e[j] = __expf(m[j] - Mw);
    float Lw = l[0] * e[0] + l[1] * e[1] + l[2] * e[2] + l[3] * e[3];
    s_m[w] = Mw; s_l[w] = Lw;
#pragma unroll
    for (int k = 0; k < 8; k++)
        s_ctx[w * 256 + h0 + k] = c[0][k] * e[0] + c[1][k] * e[1]
                                + c[2][k] * e[2] + c[3][k] * e[3];
    __syncthreads();

    float Mg = NEG_HUGE;
#pragma unroll
    for (int i = 0; i < 16; i++) Mg = fmaxf(Mg, s_m[i]);
    float Lg = 0.f;
#pragma unroll
    for (int i = 0; i < 16; i++) Lg += __expf(s_m[i] - Mg) * s_l[i];
    float invL = 1.f / Lg;

    if (tid < 256) {
        float acc = 0.f;
#pragma unroll
        for (int i = 0; i < 16; i++) acc += __expf(s_m[i] - Mg) * s_ctx[i * 256 + tid];
        acc *= invL;
        out[CTX_OFF + b * Hv + tid] = acc;
    }
    for (int t = tid; t < Tv; t += 512)
        out[ATTN_OFF + (size_t)b * Tv + t] = __expf(s_scores[t] - Mg) * invL;
}

// ---------------- K2: fused comb -> gxgh -> gru, one kernel, grid=128 ----------------
#define CW_STR 516
#define GW_STR 260
#define NBLK 128
__global__ void __launch_bounds__(256) k_mid(const int* __restrict__ tokens,
                                             const float* __restrict__ emb_table,
                                             const float* __restrict__ comb_W,
                                             const float* __restrict__ comb_b,
                                             const float* __restrict__ gru_Wih,
                                             const float* __restrict__ gru_Whh,
                                             const float* __restrict__ bih,
                                             const float* __restrict__ bhh,
                                             const float* __restrict__ hidden,
                                             float* __restrict__ out) {
    extern __shared__ float dsm[];
    int tid = threadIdx.x, bid = blockIdx.x;

    // ---- phase 1: comb ----
    if (bid < 64) {
        float* ws = dsm;
        float* xs = dsm + 32 * CW_STR;
        int n0 = (bid & 7) * 32, b0 = (bid >> 3) * 16;
        const float* ctx = out + CTX_OFF;

#pragma unroll
        for (int i = 0; i < 16; i++) {
            int id = i * 256 + tid;
            int r = id >> 7, cc = (id & 127) * 4;
            float4 v = *(const float4*)(comb_W + (size_t)(n0 + r) * 512 + cc);
            *(float4*)(ws + r * CW_STR + cc) = v;
        }
#pragma unroll
        for (int i = 0; i < 8; i++) {
            int id = i * 256 + tid;
            int r = id >> 7, cc = (id & 127) * 4;
            int gb = b0 + r;
            float4 v;
            if (cc < 256) v = *(const float4*)(emb_table + (size_t)tokens[gb] * Hv + cc);
            else          v = *(const float4*)(ctx + (size_t)gb * Hv + (cc - 256));
            *(float4*)(xs + r * 512 + cc) = v;
        }
        __syncthreads();

        int n = tid & 31, bg = tid >> 5;
        const float4* wr = (const float4*)(ws + n * CW_STR);
        const float4* x0 = (const float4*)(xs + (bg * 2 + 0) * 512);
        const float4* x1 = (const float4*)(xs + (bg * 2 + 1) * 512);
        float a0 = 0.f, a1 = 0.f;
#pragma unroll 8
        for (int k4 = 0; k4 < 128; k4++) {
            float4 wv = wr[k4];
            a0 += dot4(wv, x0[k4]);
            a1 += dot4(wv, x1[k4]);
        }
        float bvl = comb_b[n0 + n];
        g_x[(b0 + bg * 2 + 0) * Hv + n0 + n] = fmaxf(a0 + bvl, 0.f);
        g_x[(b0 + bg * 2 + 1) * Hv + n0 + n] = fmaxf(a1 + bvl, 0.f);
    }

    grid_barrier(&g_bar, NBLK);

    // ---- phase 2: gxgh ----
    for (int t = bid; t < 192; t += NBLK) {
        __syncthreads();
        float* ws = dsm;
        float* xs = dsm + 32 * GW_STR;
        int z = t >= 96;
        int rem = t - z * 96;
        int n0 = (rem % 24) * 32, b0 = (rem / 24) * 32;
        const float* A = z ? gru_Whh : gru_Wih;
        const float* B = z ? hidden : g_x;
        const float* bias = z ? bhh : bih;
        float* Y = z ? g_gh : g_gx;

#pragma unroll
        for (int i = 0; i < 8; i++) {
            int id = i * 256 + tid;
            int r = id >> 6, cc = (id & 63) * 4;
            float4 v = *(const float4*)(A + (size_t)(n0 + r) * Hv + cc);
            *(float4*)(ws + r * GW_STR + cc) = v;
        }
#pragma unroll
        for (int i = 0; i < 8; i++) {
            int id = i * 256 + tid;
            int r = id >> 6, cc = (id & 63) * 4;
            float4 v = *(const float4*)(B + (size_t)(b0 + r) * Hv + cc);
            *(float4*)(xs + r * 256 + cc) = v;
        }
        __syncthreads();

        int n = tid & 31, bg = tid >> 5;
        const float4* wr = (const float4*)(ws + n * GW_STR);
        const float4* x0 = (const float4*)(xs + (bg * 4 + 0) * 256);
        const float4* x1 = (const float4*)(xs + (bg * 4 + 1) * 256);
        const float4* x2 = (const float4*)(xs + (bg * 4 + 2) * 256);
        const float4* x3 = (const float4*)(xs + (bg * 4 + 3) * 256);
        float a0 = 0.f, a1 = 0.f, a2 = 0.f, a3 = 0.f;
#pragma unroll 8
        for (int k4 = 0; k4 < 64; k4++) {
            float4 wv = wr[k4];
            a0 += dot4(wv, x0[k4]);
            a1 += dot4(wv, x1[k4]);
            a2 += dot4(wv, x2[k4]);
            a3 += dot4(wv, x3[k4]);
        }
        float bvl = bias[n0 + n];
        Y[(size_t)(b0 + bg * 4 + 0) * 768 + n0 + n] = a0 + bvl;
        Y[(size_t)(b0 + bg * 4 + 1) * 768 + n0 + n] = a1 + bvl;
        Y[(size_t)(b0 + bg * 4 + 2) * 768 + n0 + n] = a2 + bvl;
        Y[(size_t)(b0 + bg * 4 + 3) * 768 + n0 + n] = a3 + bvl;
    }

    grid_barrier(&g_bar, NBLK);

    // ---- phase 3: gru ----
    {
        int b = bid, h = tid;
        float xr = g_gx[b * 768 + h],        hr = g_gh[b * 768 + h];
        float xz = g_gx[b * 768 + 256 + h],  hz = g_gh[b * 768 + 256 + h];
        float xn = g_gx[b * 768 + 512 + h],  hn = g_gh[b * 768 + 512 + h];
        float r = sigmoid_fast(xr + hr);
        float z = sigmoid_fast(xz + hz);
        float n = tanh_fast(xn + r * hn);
        float hprev = hidden[b * Hv + h];
        float hnew = (1.f - z) * n + z * hprev;
        out[HNEW_OFF + b * Hv + h] = hnew;
    }
}

// ---------------- K3: logits GEMM via tf32 mma.sync (R11-proven) ----------------
#define SW_STR 36
#define SB_STR 36
#define RES_STR 132
#define SW_SZ  (128 * SW_STR)
#define SB_SZ  (128 * SB_STR)
__global__ void __launch_bounds__(256, 2) k_logits(const float* __restrict__ Wv,
                                                   const float* __restrict__ out_b,
                                                   float* __restrict__ out) {
    __shared__ __align__(16) uint32_t smem[SW_SZ + SB_SZ];
    __shared__ __align__(16) float s_bias[128];
    uint32_t* s_w = smem;
    uint32_t* s_h = smem + SW_SZ;
    float* res = (float*)smem;

    int tid = threadIdx.x, wid = tid >> 5, lane = tid & 31;
    int wm = wid & 3, wn = wid >> 2;
    int vb = blockIdx.x * 128;
    int lr = lane >> 2;
    int lc = lane & 3;
    const float* hB = out + HNEW_OFF;

    if (tid < 128) s_bias[tid] = out_b[vb + tid];

    float acc[2][8][4];
#pragma unroll
    for (int mt = 0; mt < 2; mt++)
#pragma unroll
        for (int j = 0; j < 8; j++)
#pragma unroll
            for (int c = 0; c < 4; c++) acc[mt][j][c] = 0.f;

    for (int kc = 0; kc < 256; kc += 32) {
        __syncthreads();
        {
            int k4 = (tid & 7) * 4;
#pragma unroll
            for (int i = 0; i < 4; i++) {
                int v = (tid >> 3) + i * 32;
                float4 wv = *(const float4*)(Wv + (size_t)(vb + v) * 256 + kc + k4);
                uint32_t* d = s_w + v * SW_STR + k4;
                d[0] = to_tf32(wv.x); d[1] = to_tf32(wv.y);
                d[2] = to_tf32(wv.z); d[3] = to_tf32(wv.w);
            }
        }
        {
            int r = tid >> 1;
            int cbase = (tid & 1) * 16;
#pragma unroll
            for (int i = 0; i < 4; i++) {
                int c = cbase + i * 4;
                float4 hv = *(const float4*)(hB + (size_t)r * 256 + kc + c);
                uint32_t* d = s_h + r * SB_STR + c;
                d[0] = to_tf32(hv.x); d[1] = to_tf32(hv.y);
                d[2] = to_tf32(hv.z); d[3] = to_tf32(hv.w);
            }
        }
        __syncthreads();

#pragma unroll
        for (int ks = 0; ks < 4; ks++) {
            int kk = ks * 8;
            uint32_t af[2][4];
#pragma unroll
            for (int mt = 0; mt < 2; mt++) {
                int row = wm * 32 + mt * 16 + lr;
                af[mt][0] = s_w[row * SW_STR + kk + lc];
                af[mt][1] = s_w[(row + 8) * SW_STR + kk + lc];
                af[mt][2] = s_w[row * SW_STR + kk + 4 + lc];
                af[mt][3] = s_w[(row + 8) * SW_STR + kk + 4 + lc];
            }
            uint32_t bf[8][2];
#pragma unroll
            for (int j = 0; j < 8; j++) {
                int n = wn * 64 + j * 8 + lr;
                bf[j][0] = s_h[n * SB_STR + kk + lc];
                bf[j][1] = s_h[n * SB_STR + kk + 4 + lc];
            }
#pragma unroll
            for (int mt = 0; mt < 2; mt++)
#pragma unroll
                for (int j = 0; j < 8; j++)
                    mma_tf32(acc[mt][j], af[mt][0], af[mt][1], af[mt][2], af[mt][3],
                             bf[j][0], bf[j][1]);
        }
    }

    for (int h = 0; h < 2; h++) {
        __syncthreads();
        if (wn == h) {
#pragma unroll
            for (int mt = 0; mt < 2; mt++)
#pragma unroll
                for (int j = 0; j < 8; j++) {
                    int v0 = wm * 32 + mt * 16 + lr;
                    int b0 = j * 8 + lc * 2;
                    res[(b0    ) * RES_STR + v0    ] = acc[mt][j][0] + s_bias[v0];
                    res[(b0 + 1) * RES_STR + v0    ] = acc[mt][j][1] + s_bias[v0];
                    res[(b0    ) * RES_STR + v0 + 8] = acc[mt][j][2] + s_bias[v0 + 8];
                    res[(b0 + 1) * RES_STR + v0 + 8] = acc[mt][j][3] + s_bias[v0 + 8];
                }
        }
        __syncthreads();
#pragma unroll
        for (int i = 0; i < 32; i++) {
            int idx = i * 256 + tid;
            int bb = idx >> 7, v = idx & 127;
            out[(size_t)(h * 64 + bb) * Vv + vb + v] = res[bb * RES_STR + v];
        }
#pragma unroll
        for (int rr = 0; rr < 8; rr++) {
            int r = wid * 8 + rr;
            float4 x = *(const float4*)&res[r * RES_STR + lane * 4];
            float mx = fmaxf(fmaxf(x.x, x.y), fmaxf(x.z, x.w));
#pragma unroll
            for (int o = 16; o; o >>= 1) mx = fmaxf(mx, __shfl_xor_sync(0xffffffffu, mx, o));
            float se = __expf(x.x - mx) + __expf(x.y - mx) + __expf(x.z - mx) + __expf(x.w - mx);
#pragma unroll
            for (int o = 16; o; o >>= 1) se += __shfl_xor_sync(0xffffffffu, se, o);
            if (lane == 0) {
                int gb = h * 64 + r;
                g_pmax[gb * NTILES + blockIdx.x] = mx;   // [b][tile]
                g_psum[gb * NTILES + blockIdx.x] = se;
            }
        }
    }
}

// ---------------- K4: fused lse + subtract, prefetched, y-split 16 ----------------
__global__ void __launch_bounds__(256) k_tail(float* __restrict__ out) {
    int b = blockIdx.x, y = blockIdx.y;
    int tid = threadIdx.x, wid = tid >> 5, lane = tid & 31;
    __shared__ float s_rm[8], s_rl[8];

    // prefetch this block's 500-float4 segment before the reduce
    float4* row = (float4*)(out + (size_t)b * Vv) + y * 500;
    float4 xv[2];
    int nv = 0;
#pragma unroll
    for (int i = 0; i < 2; i++) {
        int v = i * 256 + tid;
        if (v < 500) { xv[i] = row[v]; nv = i + 1; }
    }

    // coalesced reduce of 250 partials for row b (L2-resident after first block)
    float m = NEG_HUGE, l = 0.f;
    if (tid < NTILES) {
        m = g_pmax[b * NTILES + tid];
        l = g_psum[b * NTILES + tid];
    }
#pragma unroll
    for (int o = 16; o; o >>= 1) {
        float m2 = __shfl_xor_sync(0xffffffffu, m, o);
        float l2 = __shfl_xor_sync(0xffffffffu, l, o);
        float nm = fmaxf(m, m2);
        l = l * __expf(m - nm) + l2 * __expf(m2 - nm);
        m = nm;
    }
    if (lane == 0) { s_rm[wid] = m; s_rl[wid] = l; }
    __syncthreads();
    float M = NEG_HUGE;
#pragma unroll
    for (int i = 0; i < 8; i++) M = fmaxf(M, s_rm[i]);
    float L = 0.f;
#pragma unroll
    for (int i = 0; i < 8; i++) L += s_rl[i] * __expf(s_rm[i] - M);
    float lse = M + logf(L);

#pragma unroll
    for (int i = 0; i < 2; i++) {
        int v = i * 256 + tid;
        if (i < nv) {
            float4 x = xv[i];
            x.x -= lse; x.y -= lse; x.z -= lse; x.w -= lse;
            row[v] = x;
        }
    }
}

// ---------------- launch ----------------
extern "C" void kernel_launch(void* const* d_in, const int* in_sizes, int n_in,
                              void* d_out, int out_size) {
    const int*   tokens    = (const int*)d_in[0];
    const float* hidden    = (const float*)d_in[1];
    const float* enc       = (const float*)d_in[2];
    const float* emb_table = (const float*)d_in[3];
    const float* attn_W    = (const float*)d_in[4];
    const float* attn_b    = (const float*)d_in[5];
    const float* comb_W    = (const float*)d_in[6];
    const float* comb_b    = (const float*)d_in[7];
    const float* gru_Wih   = (const float*)d_in[8];
    const float* gru_Whh   = (const float*)d_in[9];
    const float* gru_bih   = (const float*)d_in[10];
    const float* gru_bhh   = (const float*)d_in[11];
    const float* out_W     = (const float*)d_in[12];
    const float* out_b     = (const float*)d_in[13];
    float* out = (float*)d_out;

    const int M_SMEM = (32 * CW_STR + 16 * 512) * 4;   // 98,816 B
    cudaFuncSetAttribute(k_mid, cudaFuncAttributeMaxDynamicSharedMemorySize, M_SMEM);

    k_attn<<<Bv, 512>>>(enc, attn_W, hidden, attn_b, out);
    k_mid<<<NBLK, 256, M_SMEM>>>(tokens, emb_table, comb_W, comb_b,
                                 gru_Wih, gru_Whh, gru_bih, gru_bhh, hidden, out);
    k_logits<<<NTILES, 256>>>(out_W, out_b, out);
    k_tail<<<dim3(Bv, 16), 256>>>(out);
}

// round 15
// speedup vs baseline: 1.1761x; 1.0064x over previous
#include <cuda_runtime.h>
#include <cuda_bf16.h>
#include <cstdint>

#define Bv   128
#define Hv   256
#define Tv   2048
#define Vv   32000
#define NTILES 250            // Vv / 128

#define LOGP_OFF  0
#define HNEW_OFF  (Bv*Vv)                 // 4,096,000
#define ATTN_OFF  (HNEW_OFF + Bv*Hv)      // 4,128,768
#define CTX_OFF   (ATTN_OFF + Bv*Tv)      // 4,390,912

#define NEG_HUGE  (-3.402823466e38f)

// ---------------- scratch ----------------
__device__ __align__(16) float g_x[Bv * Hv];       // relu(comb) [b][n]
__device__ __align__(16) float g_gx[Bv * 3 * Hv];
__device__ __align__(16) float g_gh[Bv * 3 * Hv];
__device__ __align__(16) float g_pmax[Bv * NTILES];  // [b][tile] coalesced
__device__ __align__(16) float g_psum[Bv * NTILES];
__device__ unsigned long long g_bar = 0ull;        // k_mid barrier (nb=128)

// ---------------- helpers ----------------
__device__ __forceinline__ uint32_t to_tf32(float x) {
    uint32_t r;
    asm("cvt.rna.tf32.f32 %0, %1;" : "=r"(r) : "f"(x));
    return r;
}
__device__ __forceinline__ void mma_tf32(float* c, uint32_t a0, uint32_t a1,
                                         uint32_t a2, uint32_t a3,
                                         uint32_t b0, uint32_t b1) {
    asm("mma.sync.aligned.m16n8k8.row.col.f32.tf32.tf32.f32 "
        "{%0,%1,%2,%3},{%4,%5,%6,%7},{%8,%9},{%0,%1,%2,%3};"
        : "+f"(c[0]), "+f"(c[1]), "+f"(c[2]), "+f"(c[3])
        : "r"(a0), "r"(a1), "r"(a2), "r"(a3), "r"(b0), "r"(b1));
}
__device__ __forceinline__ float tanh_fast(float x) {
    float r;
    asm("tanh.approx.f32 %0, %1;" : "=f"(r) : "f"(x));
    return r;
}
__device__ __forceinline__ float sigmoid_fast(float x) {
    return 0.5f * tanh_fast(0.5f * x) + 0.5f;
}
__device__ __forceinline__ float dot4(float4 a, float4 b) {
    return a.x * b.x + a.y * b.y + a.z * b.z + a.w * b.w;
}
__device__ __forceinline__ void grid_barrier(unsigned long long* bar, int nb) {
    __syncthreads();
    __threadfence();
    if (threadIdx.x == 0) {
        unsigned long long old = atomicAdd(bar, 1ull);
        unsigned long long target = (old / nb + 1ull) * (unsigned long long)nb;
        unsigned long long v;
        do {
            asm volatile("ld.global.acquire.gpu.u64 %0, [%1];"
                         : "=l"(v) : "l"(bar));
        } while (v < target);
    }
    __syncthreads();
}

// ---------------- K1: fused attention (R11-proven: single pass, 4 chains/warp) ----------------
__global__ void __launch_bounds__(512) k_attn(const float* __restrict__ enc,
                                              const float* __restrict__ attn_W,
                                              const float* __restrict__ hidden,
                                              const float* __restrict__ attn_b,
                                              float* __restrict__ out) {
    int b = blockIdx.x;
    int tid = threadIdx.x, w = tid >> 5, lane = tid & 31;
    __shared__ float s_scores[Tv];
    __shared__ float s_m[16], s_l[16];
    __shared__ __align__(16) float s_ctx[16 * 256];
    __shared__ float s_shred[8];

    float hv = 0.f;
    if (tid < 256) hv = hidden[b * Hv + tid] * attn_W[tid];
#pragma unroll
    for (int o = 16; o; o >>= 1) hv += __shfl_xor_sync(0xffffffffu, hv, o);
    if (lane == 0 && w < 8) s_shred[w] = hv;
    __syncthreads();
    float sh = attn_b[0];
#pragma unroll
    for (int i = 0; i < 8; i++) sh += s_shred[i];

    int h0 = lane * 8;
    float4 we0 = *(const float4*)(attn_W + Hv + h0);
    float4 we1 = *(const float4*)(attn_W + Hv + h0 + 4);
    float wv[8] = {we0.x, we0.y, we0.z, we0.w, we1.x, we1.y, we1.z, we1.w};

    float m[4], l[4], c[4][8];
#pragma unroll
    for (int j = 0; j < 4; j++) {
        m[j] = NEG_HUGE; l[j] = 0.f;
#pragma unroll
        for (int k = 0; k < 8; k++) c[j][k] = 0.f;
    }

    const float* base = enc + (size_t)b * Hv + h0;
    const size_t STR = (size_t)Bv * Hv;

    float4 P[4][2];
#pragma unroll
    for (int j = 0; j < 4; j++) {
        const float4* p = (const float4*)(base + (size_t)(w + j * 16) * STR);
        P[j][0] = p[0]; P[j][1] = p[1];
    }

    for (int i = 0; i < 32; i++) {
        float4 C0[4], C1[4];
#pragma unroll
        for (int j = 0; j < 4; j++) { C0[j] = P[j][0]; C1[j] = P[j][1]; }
        if (i < 31) {
            int tb = (i + 1) * 64 + w;
#pragma unroll
            for (int j = 0; j < 4; j++) {
                const float4* p = (const float4*)(base + (size_t)(tb + j * 16) * STR);
                P[j][0] = p[0]; P[j][1] = p[1];
            }
        }

        float ea[4][8];
#pragma unroll
        for (int j = 0; j < 4; j++) {
            ea[j][0] = C0[j].x; ea[j][1] = C0[j].y; ea[j][2] = C0[j].z; ea[j][3] = C0[j].w;
            ea[j][4] = C1[j].x; ea[j][5] = C1[j].y; ea[j][6] = C1[j].z; ea[j][7] = C1[j].w;
        }

        float s[4];
#pragma unroll
        for (int j = 0; j < 4; j++) {
            float v = 0.f;
#pragma unroll
            for (int k = 0; k < 8; k++) v += ea[j][k] * wv[k];
            s[j] = v;
        }
#pragma unroll
        for (int o = 16; o; o >>= 1) {
#pragma unroll
            for (int j = 0; j < 4; j++)
                s[j] += __shfl_xor_sync(0xffffffffu, s[j], o);
        }
#pragma unroll
        for (int j = 0; j < 4; j++) s[j] += sh;

        if (lane == 0) {
            int t0 = i * 64 + w;
#pragma unroll
            for (int j = 0; j < 4; j++) s_scores[t0 + j * 16] = s[j];
        }

#pragma unroll
        for (int j = 0; j < 4; j++) {
            if (s[j] <= m[j]) {
                float p = __expf(s[j] - m[j]);
                l[j] += p;
#pragma unroll
                for (int k = 0; k < 8; k++) c[j][k] += p * ea[j][k];
            } else {
                float cc = __expf(m[j] - s[j]);
                l[j] = l[j] * cc + 1.f;
#pragma unroll
                for (int k = 0; k < 8; k++) c[j][k] = c[j][k] * cc + ea[j][k];
                m[j] = s[j];
            }
        }
    }

    float Mw = fmaxf(fmaxf(m[0], m[1]), fmaxf(m[2], m[3]));
    float e[4];
#pragma unroll
    for (int j = 0; j < 4; j++) e[j] = __expf(m[j] - Mw);
    float Lw = l[0] * e[0] + l[1] * e[1] + l[2] * e[2] + l[3] * e[3];
    s_m[w] = Mw; s_l[w] = Lw;
#pragma unroll
    for (int k = 0; k < 8; k++)
        s_ctx[w * 256 + h0 + k] = c[0][k] * e[0] + c[1][k] * e[1]
                                + c[2][k] * e[2] + c[3][k] * e[3];
    __syncthreads();

    float Mg = NEG_HUGE;
#pragma unroll
    for (int i = 0; i < 16; i++) Mg = fmaxf(Mg, s_m[i]);
    float Lg = 0.f;
#pragma unroll
    for (int i = 0; i < 16; i++) Lg += __expf(s_m[i] - Mg) * s_l[i];
    float invL = 1.f / Lg;

    if (tid < 256) {
        float acc = 0.f;
#pragma unroll
        for (int i = 0; i < 16; i++) acc += __expf(s_m[i] - Mg) * s_ctx[i * 256 + tid];
        acc *= invL;
        out[CTX_OFF + b * Hv + tid] = acc;
    }
    for (int t = tid; t < Tv; t += 512)
        out[ATTN_OFF + (size_t)b * Tv + t] = __expf(s_scores[t] - Mg) * invL;
}

// ---------------- K2: fused comb -> gxgh -> gru, one kernel, grid=128 ----------------
#define CW_STR 516
#define GW_STR 260
#define NBLK 128
__global__ void __launch_bounds__(256) k_mid(const int* __restrict__ tokens,
                                             const float* __restrict__ emb_table,
                                             const float* __restrict__ comb_W,
                                             const float* __restrict__ comb_b,
                                             const float* __restrict__ gru_Wih,
                                             const float* __restrict__ gru_Whh,
                                             const float* __restrict__ bih,
                                             const float* __restrict__ bhh,
                                             const float* __restrict__ hidden,
                                             float* __restrict__ out) {
    extern __shared__ float dsm[];
    int tid = threadIdx.x, bid = blockIdx.x;

    // ---- phase 1: comb ----
    if (bid < 64) {
        float* ws = dsm;
        float* xs = dsm + 32 * CW_STR;
        int n0 = (bid & 7) * 32, b0 = (bid >> 3) * 16;
        const float* ctx = out + CTX_OFF;

#pragma unroll
        for (int i = 0; i < 16; i++) {
            int id = i * 256 + tid;
            int r = id >> 7, cc = (id & 127) * 4;
            float4 v = *(const float4*)(comb_W + (size_t)(n0 + r) * 512 + cc);
            *(float4*)(ws + r * CW_STR + cc) = v;
        }
#pragma unroll
        for (int i = 0; i < 8; i++) {
            int id = i * 256 + tid;
            int r = id >> 7, cc = (id & 127) * 4;
            int gb = b0 + r;
            float4 v;
            if (cc < 256) v = *(const float4*)(emb_table + (size_t)tokens[gb] * Hv + cc);
            else          v = *(const float4*)(ctx + (size_t)gb * Hv + (cc - 256));
            *(float4*)(xs + r * 512 + cc) = v;
        }
        __syncthreads();

        int n = tid & 31, bg = tid >> 5;
        const float4* wr = (const float4*)(ws + n * CW_STR);
        const float4* x0 = (const float4*)(xs + (bg * 2 + 0) * 512);
        const float4* x1 = (const float4*)(xs + (bg * 2 + 1) * 512);
        float a0 = 0.f, a1 = 0.f;
#pragma unroll 8
        for (int k4 = 0; k4 < 128; k4++) {
            float4 wv = wr[k4];
            a0 += dot4(wv, x0[k4]);
            a1 += dot4(wv, x1[k4]);
        }
        float bvl = comb_b[n0 + n];
        g_x[(b0 + bg * 2 + 0) * Hv + n0 + n] = fmaxf(a0 + bvl, 0.f);
        g_x[(b0 + bg * 2 + 1) * Hv + n0 + n] = fmaxf(a1 + bvl, 0.f);
    }

    grid_barrier(&g_bar, NBLK);

    // ---- phase 2: gxgh ----
    for (int t = bid; t < 192; t += NBLK) {
        __syncthreads();
        float* ws = dsm;
        float* xs = dsm + 32 * GW_STR;
        int z = t >= 96;
        int rem = t - z * 96;
        int n0 = (rem % 24) * 32, b0 = (rem / 24) * 32;
        const float* A = z ? gru_Whh : gru_Wih;
        const float* B = z ? hidden : g_x;
        const float* bias = z ? bhh : bih;
        float* Y = z ? g_gh : g_gx;

#pragma unroll
        for (int i = 0; i < 8; i++) {
            int id = i * 256 + tid;
            int r = id >> 6, cc = (id & 63) * 4;
            float4 v = *(const float4*)(A + (size_t)(n0 + r) * Hv + cc);
            *(float4*)(ws + r * GW_STR + cc) = v;
        }
#pragma unroll
        for (int i = 0; i < 8; i++) {
            int id = i * 256 + tid;
            int r = id >> 6, cc = (id & 63) * 4;
            float4 v = *(const float4*)(B + (size_t)(b0 + r) * Hv + cc);
            *(float4*)(xs + r * 256 + cc) = v;
        }
        __syncthreads();

        int n = tid & 31, bg = tid >> 5;
        const float4* wr = (const float4*)(ws + n * GW_STR);
        const float4* x0 = (const float4*)(xs + (bg * 4 + 0) * 256);
        const float4* x1 = (const float4*)(xs + (bg * 4 + 1) * 256);
        const float4* x2 = (const float4*)(xs + (bg * 4 + 2) * 256);
        const float4* x3 = (const float4*)(xs + (bg * 4 + 3) * 256);
        float a0 = 0.f, a1 = 0.f, a2 = 0.f, a3 = 0.f;
#pragma unroll 8
        for (int k4 = 0; k4 < 64; k4++) {
            float4 wv = wr[k4];
            a0 += dot4(wv, x0[k4]);
            a1 += dot4(wv, x1[k4]);
            a2 += dot4(wv, x2[k4]);
            a3 += dot4(wv, x3[k4]);
        }
        float bvl = bias[n0 + n];
        Y[(size_t)(b0 + bg * 4 + 0) * 768 + n0 + n] = a0 + bvl;
        Y[(size_t)(b0 + bg * 4 + 1) * 768 + n0 + n] = a1 + bvl;
        Y[(size_t)(b0 + bg * 4 + 2) * 768 + n0 + n] = a2 + bvl;
        Y[(size_t)(b0 + bg * 4 + 3) * 768 + n0 + n] = a3 + bvl;
    }

    grid_barrier(&g_bar, NBLK);

    // ---- phase 3: gru ----
    {
        int b = bid, h = tid;
        float xr = g_gx[b * 768 + h],        hr = g_gh[b * 768 + h];
        float xz = g_gx[b * 768 + 256 + h],  hz = g_gh[b * 768 + 256 + h];
        float xn = g_gx[b * 768 + 512 + h],  hn = g_gh[b * 768 + 512 + h];
        float r = sigmoid_fast(xr + hr);
        float z = sigmoid_fast(xz + hz);
        float n = tanh_fast(xn + r * hn);
        float hprev = hidden[b * Hv + h];
        float hnew = (1.f - z) * n + z * hprev;
        out[HNEW_OFF + b * Hv + h] = hnew;
    }
}

// ---------------- K3: logits GEMM via tf32 mma.sync (R11-proven) ----------------
#define SW_STR 36
#define SB_STR 36
#define RES_STR 132
#define SW_SZ  (128 * SW_STR)
#define SB_SZ  (128 * SB_STR)
__global__ void __launch_bounds__(256, 2) k_logits(const float* __restrict__ Wv,
                                                   const float* __restrict__ out_b,
                                                   float* __restrict__ out) {
    __shared__ __align__(16) uint32_t smem[SW_SZ + SB_SZ];
    __shared__ __align__(16) float s_bias[128];
    uint32_t* s_w = smem;
    uint32_t* s_h = smem + SW_SZ;
    float* res = (float*)smem;

    int tid = threadIdx.x, wid = tid >> 5, lane = tid & 31;
    int wm = wid & 3, wn = wid >> 2;
    int vb = blockIdx.x * 128;
    int lr = lane >> 2;
    int lc = lane & 3;
    const float* hB = out + HNEW_OFF;

    if (tid < 128) s_bias[tid] = out_b[vb + tid];

    float acc[2][8][4];
#pragma unroll
    for (int mt = 0; mt < 2; mt++)
#pragma unroll
        for (int j = 0; j < 8; j++)
#pragma unroll
            for (int c = 0; c < 4; c++) acc[mt][j][c] = 0.f;

    for (int kc = 0; kc < 256; kc += 32) {
        __syncthreads();
        {
            int k4 = (tid & 7) * 4;
#pragma unroll
            for (int i = 0; i < 4; i++) {
                int v = (tid >> 3) + i * 32;
                float4 wv = *(const float4*)(Wv + (size_t)(vb + v) * 256 + kc + k4);
                uint32_t* d = s_w + v * SW_STR + k4;
                d[0] = to_tf32(wv.x); d[1] = to_tf32(wv.y);
                d[2] = to_tf32(wv.z); d[3] = to_tf32(wv.w);
            }
        }
        {
            int r = tid >> 1;
            int cbase = (tid & 1) * 16;
#pragma unroll
            for (int i = 0; i < 4; i++) {
                int c = cbase + i * 4;
                float4 hv = *(const float4*)(hB + (size_t)r * 256 + kc + c);
                uint32_t* d = s_h + r * SB_STR + c;
                d[0] = to_tf32(hv.x); d[1] = to_tf32(hv.y);
                d[2] = to_tf32(hv.z); d[3] = to_tf32(hv.w);
            }
        }
        __syncthreads();

#pragma unroll
        for (int ks = 0; ks < 4; ks++) {
            int kk = ks * 8;
            uint32_t af[2][4];
#pragma unroll
            for (int mt = 0; mt < 2; mt++) {
                int row = wm * 32 + mt * 16 + lr;
                af[mt][0] = s_w[row * SW_STR + kk + lc];
                af[mt][1] = s_w[(row + 8) * SW_STR + kk + lc];
                af[mt][2] = s_w[row * SW_STR + kk + 4 + lc];
                af[mt][3] = s_w[(row + 8) * SW_STR + kk + 4 + lc];
            }
            uint32_t bf[8][2];
#pragma unroll
            for (int j = 0; j < 8; j++) {
                int n = wn * 64 + j * 8 + lr;
                bf[j][0] = s_h[n * SB_STR + kk + lc];
                bf[j][1] = s_h[n * SB_STR + kk + 4 + lc];
            }
#pragma unroll
            for (int mt = 0; mt < 2; mt++)
#pragma unroll
                for (int j = 0; j < 8; j++)
                    mma_tf32(acc[mt][j], af[mt][0], af[mt][1], af[mt][2], af[mt][3],
                             bf[j][0], bf[j][1]);
        }
    }

    for (int h = 0; h < 2; h++) {
        __syncthreads();
        if (wn == h) {
#pragma unroll
            for (int mt = 0; mt < 2; mt++)
#pragma unroll
                for (int j = 0; j < 8; j++) {
                    int v0 = wm * 32 + mt * 16 + lr;
                    int b0 = j * 8 + lc * 2;
                    res[(b0    ) * RES_STR + v0    ] = acc[mt][j][0] + s_bias[v0];
                    res[(b0 + 1) * RES_STR + v0    ] = acc[mt][j][1] + s_bias[v0];
                    res[(b0    ) * RES_STR + v0 + 8] = acc[mt][j][2] + s_bias[v0 + 8];
                    res[(b0 + 1) * RES_STR + v0 + 8] = acc[mt][j][3] + s_bias[v0 + 8];
                }
        }
        __syncthreads();
#pragma unroll
        for (int i = 0; i < 32; i++) {
            int idx = i * 256 + tid;
            int bb = idx >> 7, v = idx & 127;
            out[(size_t)(h * 64 + bb) * Vv + vb + v] = res[bb * RES_STR + v];
        }
#pragma unroll
        for (int rr = 0; rr < 8; rr++) {
            int r = wid * 8 + rr;
            float4 x = *(const float4*)&res[r * RES_STR + lane * 4];
            float mx = fmaxf(fmaxf(x.x, x.y), fmaxf(x.z, x.w));
#pragma unroll
            for (int o = 16; o; o >>= 1) mx = fmaxf(mx, __shfl_xor_sync(0xffffffffu, mx, o));
            float se = __expf(x.x - mx) + __expf(x.y - mx) + __expf(x.z - mx) + __expf(x.w - mx);
#pragma unroll
            for (int o = 16; o; o >>= 1) se += __shfl_xor_sync(0xffffffffu, se, o);
            if (lane == 0) {
                int gb = h * 64 + r;
                g_pmax[gb * NTILES + blockIdx.x] = mx;   // [b][tile]
                g_psum[gb * NTILES + blockIdx.x] = se;
            }
        }
    }
}

// ---------------- K4: fused lse + subtract, two-pass reduce (1 exp/thread) ----------------
__global__ void __launch_bounds__(256) k_tail(float* __restrict__ out) {
    int b = blockIdx.x, y = blockIdx.y;
    int tid = threadIdx.x, wid = tid >> 5, lane = tid & 31;
    __shared__ float s_r[8];

    // prefetch this block's 500-float4 segment before the reduce
    float4* row = (float4*)(out + (size_t)b * Vv) + y * 500;
    float4 xv[2];
    int nv = 0;
#pragma unroll
    for (int i = 0; i < 2; i++) {
        int v = i * 256 + tid;
        if (v < 500) { xv[i] = row[v]; nv = i + 1; }
    }

    // pass 1: M = max(m_i)  (pure fmax, no MUFU)
    float mi = NEG_HUGE, si = 0.f;
    if (tid < NTILES) {
        mi = g_pmax[b * NTILES + tid];
        si = g_psum[b * NTILES + tid];
    }
    float m = mi;
#pragma unroll
    for (int o = 16; o; o >>= 1) m = fmaxf(m, __shfl_xor_sync(0xffffffffu, m, o));
    if (lane == 0) s_r[wid] = m;
    __syncthreads();
    float M = NEG_HUGE;
#pragma unroll
    for (int i = 0; i < 8; i++) M = fmaxf(M, s_r[i]);
    __syncthreads();

    // pass 2: L = sum se_i * exp(m_i - M)  (one exp per thread, pure-add butterfly)
    float contrib = (tid < NTILES) ? si * __expf(mi - M) : 0.f;
#pragma unroll
    for (int o = 16; o; o >>= 1) contrib += __shfl_xor_sync(0xffffffffu, contrib, o);
    if (lane == 0) s_r[wid] = contrib;
    __syncthreads();
    float L = 0.f;
#pragma unroll
    for (int i = 0; i < 8; i++) L += s_r[i];
    float lse = M + logf(L);

#pragma unroll
    for (int i = 0; i < 2; i++) {
        int v = i * 256 + tid;
        if (i < nv) {
            float4 x = xv[i];
            x.x -= lse; x.y -= lse; x.z -= lse; x.w -= lse;
            row[v] = x;
        }
    }
}

// ---------------- launch ----------------
extern "C" void kernel_launch(void* const* d_in, const int* in_sizes, int n_in,
                              void* d_out, int out_size) {
    const int*   tokens    = (const int*)d_in[0];
    const float* hidden    = (const float*)d_in[1];
    const float* enc       = (const float*)d_in[2];
    const float* emb_table = (const float*)d_in[3];
    const float* attn_W    = (const float*)d_in[4];
    const float* attn_b    = (const float*)d_in[5];
    const float* comb_W    = (const float*)d_in[6];
    const float* comb_b    = (const float*)d_in[7];
    const float* gru_Wih   = (const float*)d_in[8];
    const float* gru_Whh   = (const float*)d_in[9];
    const float* gru_bih   = (const float*)d_in[10];
    const float* gru_bhh   = (const float*)d_in[11];
    const float* out_W     = (const float*)d_in[12];
    const float* out_b     = (const float*)d_in[13];
    float* out = (float*)d_out;

    const int M_SMEM = (32 * CW_STR + 16 * 512) * 4;   // 98,816 B
    cudaFuncSetAttribute(k_mid, cudaFuncAttributeMaxDynamicSharedMemorySize, M_SMEM);

    k_attn<<<Bv, 512>>>(enc, attn_W, hidden, attn_b, out);
    k_mid<<<NBLK, 256, M_SMEM>>>(tokens, emb_table, comb_W, comb_b,
                                 gru_Wih, gru_Whh, gru_bih, gru_bhh, hidden, out);
    k_logits<<<NTILES, 256>>>(out_W, out_b, out);
    k_tail<<<dim3(Bv, 16), 256>>>(out);
}